// round 15
// baseline (speedup 1.0000x reference)
#include <cuda_runtime.h>
#include <math.h>

#define NNODES 20000
#define NEDGES 50000
#define HID 128
#define OUTD 64
#define NPAIRS 128
#define UTOT 256
#define DEGCAP 64
#define MCAP (UTOT * DEGCAP)   /* 16384 */
#define ACAPN (UTOT + MCAP)    /* 16640 */
#define TFS (ACAPN * HID)
#define TM 8
#define NB 148
#define NTHREADS 512
#define UPB 4
#define NUNITS (UPB * NB)      /* 592 */
#define CPB 8
#define GRP 4
#define GSZ 37
#define EPB 338                /* edges per block: 148*338 >= 50000 */
#define ENCMAX 0x7fffffff
#define SCALE 0.17677669529663687f

// ---------------- device scratch (zero-init == clean state) ----------------
__device__ int g_owner[NNODES];      // 0 = unmarked, else ENCMAX - u
__device__ int g_node2slot[NNODES];  // 0 = none, -1 = lock, else slot+1
__device__ int g_degRaw[UTOT];
__device__ int g_rawEdge[MCAP];
__device__ int g_rawNbr[MCAP];
__device__ int g_srtEdge[MCAP];
__device__ int g_srtNbr[MCAP];
__device__ int g_deg[UTOT];
__device__ int g_odeg[UTOT];         // owned? deg : 0
__device__ int g_incBase[UTOT];
__device__ int g_tslot[UTOT];
__device__ int g_entrySlot[MCAP];
__device__ int g_entryTIdx[MCAP];
__device__ int g_activeNodes[ACAPN];
__device__ int g_activeCount;
__device__ int g_totalEntries;
// tree barrier: per-group arrive counters (separate lines), root, published gen
__device__ __align__(128) unsigned g_grpArr[GRP * 32];
__device__ __align__(128) unsigned g_rootArr[32];
__device__ __align__(128) unsigned g_genPub[32];

__device__ float g_x[ACAPN * HID];
__device__ float g_tf[2 * TFS];             // [layer][slot][HID]
__device__ float g_tfeat[2 * MCAP * HID];   // [layer][u*DEGCAP+i][HID]
__device__ float g_K[MCAP * HID];
__device__ float g_V[MCAP * HID];
__device__ float g_q[UTOT * HID];
__device__ float g_WT[19 * HID * HID];
// transposed: 0:in 1:ft0 2:ft1 3,4:te2 5,6:q 7,8:k 9,10:v 11,12:ao 13,14:op
// 15:o1 16:o2(R=64) 17:l1 18:l2(R=64)

__device__ __forceinline__ const float* WT(int m) { return g_WT + m * HID * HID; }

// ---- two-level tree barrier: group atomics in parallel, one-hop release ----
__device__ __forceinline__ void gsync(unsigned& gen) {
    __syncthreads();
    if (threadIdx.x == 0) {
        gen++;
        int g = blockIdx.x & (GRP - 1);
        unsigned old;
        asm volatile("atom.add.release.gpu.u32 %0, [%1], 1;"
                     : "=r"(old) : "l"(&g_grpArr[g * 32]) : "memory");
        if (old == gen * GSZ - 1u) {
            unsigned ro;
            asm volatile("atom.add.release.gpu.u32 %0, [%1], 1;"
                         : "=r"(ro) : "l"(&g_rootArr[0]) : "memory");
            if (ro == gen * GRP - 1u) {
                __threadfence();
                asm volatile("st.release.gpu.u32 [%0], %1;"
                             ::"l"(&g_genPub[0]), "r"(gen) : "memory");
            }
        }
        unsigned v;
        do {
            asm volatile("ld.acquire.gpu.u32 %0, [%1];"
                         : "=r"(v) : "l"(&g_genPub[0]) : "memory");
        } while (v < gen);
    }
    __syncthreads();
}

__device__ __forceinline__ void usync(int unit) {
    asm volatile("bar.sync %0, 128;" ::"r"(unit + 1) : "memory");
}
__device__ __forceinline__ void hsync(int half) {
    asm volatile("bar.sync %0, 256;" ::"r"(half + 5) : "memory");
}

__device__ __forceinline__ void ensure_slot(int n) {
    if (g_node2slot[n] == 0) {
        if (atomicCAS(&g_node2slot[n], 0, -1) == 0) {
            int s = atomicAdd(&g_activeCount, 1);
            g_activeNodes[s] = n;
            __threadfence();
            g_node2slot[n] = s + 1;
        }
    }
}

// one 128x32 transpose tile job (halves use independent named barriers)
__device__ __forceinline__ void transpose_job(
    int job, float* sh, int htid, int half,
    const float* inW, const float* ftW, const float* teW2, const float* aiW,
    const float* aoW, const float* opW, const float* o1W, const float* o2W,
    const float* l1W, const float* l2W) {
    int m = job >> 4, t = job & 15;
    const float* src;
    int R = HID;
    switch (m) {
        case 0: src = inW; break;
        case 1: case 2: src = ftW + (size_t)(m - 1) * HID * HID; break;
        case 3: case 4: src = teW2 + (size_t)(m - 3) * HID * HID; break;
        case 5: case 6: src = aiW + (size_t)(m - 5) * 3 * HID * HID; break;
        case 7: case 8: src = aiW + (size_t)(m - 7) * 3 * HID * HID + HID * HID; break;
        case 9: case 10: src = aiW + (size_t)(m - 9) * 3 * HID * HID + 2 * HID * HID; break;
        case 11: case 12: src = aoW + (size_t)(m - 11) * HID * HID; break;
        case 13: case 14: src = opW + (size_t)(m - 13) * HID * HID; break;
        case 15: src = o1W; break;
        case 16: src = o2W; R = OUTD; break;
        case 17: src = l1W; break;
        default: src = l2W; R = OUTD; break;
    }
    int tr = t >> 2, tc = t & 3;
    if (tr * 32 >= R) return;
    int x = htid & 31, y0 = htid >> 5;
    float* dst = g_WT + (size_t)m * HID * HID;
#pragma unroll
    for (int k = 0; k < 4; k++) {
        int y = y0 + 8 * k;
        sh[y * 33 + x] = src[(size_t)(tr * 32 + y) * HID + tc * 32 + x];
    }
    hsync(half);
#pragma unroll
    for (int k = 0; k < 4; k++) {
        int y = y0 + 8 * k;
        dst[(size_t)(tc * 32 + y) * R + tr * 32 + x] = sh[x * 33 + y];
    }
    hsync(half);
}

// Xs: TM x HID shared; Wt: [k][o]; write rows to out (optional relu on input)
template <int RELUIN>
__device__ __forceinline__ void tile_core(const float* Xs, int nrows,
                                          const float* __restrict__ Wt,
                                          const float* __restrict__ b,
                                          float* __restrict__ out, int row0, int ut) {
    float acc[TM];
#pragma unroll
    for (int i = 0; i < TM; i++) acc[i] = 0.f;
    const float4* X4 = reinterpret_cast<const float4*>(Xs);
#pragma unroll 8
    for (int k4 = 0; k4 < HID / 4; k4++) {
        const float* wp = Wt + (k4 * 4) * HID + ut;
        float w0 = wp[0];
        float w1 = wp[HID];
        float w2 = wp[2 * HID];
        float w3 = wp[3 * HID];
#pragma unroll
        for (int i = 0; i < TM; i++) {
            float4 x = X4[i * (HID / 4) + k4];
            if (RELUIN) {
                x.x = fmaxf(x.x, 0.f); x.y = fmaxf(x.y, 0.f);
                x.z = fmaxf(x.z, 0.f); x.w = fmaxf(x.w, 0.f);
            }
            acc[i] += x.x * w0 + x.y * w1 + x.z * w2 + x.w * w3;
        }
    }
    float bb = b ? b[ut] : 0.f;
    for (int i = 0; i < nrows; i++) out[(size_t)(row0 + i) * HID + ut] = acc[i] + bb;
}
#define tile_compute tile_core<0>
#define tile_compute_relu tile_core<1>

// shared x [128] dot columns of Wt -> one output per thread
__device__ __forceinline__ float gemv128(const float* xs, const float* __restrict__ Wt,
                                         int ut) {
    float a0 = 0.f, a1 = 0.f, a2 = 0.f, a3 = 0.f;
#pragma unroll 4
    for (int k = 0; k < HID; k += 4) {
        a0 += xs[k] * Wt[k * HID + ut];
        a1 += xs[k + 1] * Wt[(k + 1) * HID + ut];
        a2 += xs[k + 2] * Wt[(k + 2) * HID + ut];
        a3 += xs[k + 3] * Wt[(k + 3) * HID + ut];
    }
    return (a0 + a1) + (a2 + a3);
}

__global__ __launch_bounds__(NTHREADS, 1) void k_main(
    const float* __restrict__ nf, const int* __restrict__ ei,
    const float* __restrict__ ets, const int* __restrict__ tp,
    const float* __restrict__ inW, const float* __restrict__ inb,
    const float* __restrict__ teW1, const float* __restrict__ teb1,
    const float* __restrict__ teW2, const float* __restrict__ teb2,
    const float* __restrict__ aiW, const float* __restrict__ aib,
    const float* __restrict__ aoW, const float* __restrict__ aob,
    const float* __restrict__ ftW, const float* __restrict__ ftb,
    const float* __restrict__ opW, const float* __restrict__ opb,
    const float* __restrict__ o1W, const float* __restrict__ o1b,
    const float* __restrict__ o2W, const float* __restrict__ o2b,
    const float* __restrict__ l1W, const float* __restrict__ l1b,
    const float* __restrict__ l2W, const float* __restrict__ l2b,
    const float* __restrict__ l3W, const float* __restrict__ l3b,
    float* __restrict__ out) {
    __shared__ __align__(16) float sX[UPB * TM * HID];   // 16KB
    __shared__ __align__(16) float sY[UPB * TM * HID];   // 16KB (x tiles)
    __shared__ __align__(16) float sAux[UPB * 768];      // 12KB
    int tid = threadIdx.x;
    int unit = tid >> 7;
    int ut = tid & 127;
    int half = tid >> 8;
    int htid = tid & 255;
    int bid = blockIdx.x;
    unsigned gen;
    {
        unsigned v;
        asm volatile("ld.acquire.gpu.u32 %0, [%1];"
                     : "=r"(v) : "l"(&g_genPub[0]) : "memory");
        gen = v;
    }

    // ===== P0: redundant mark + private edge-scan chunk + weight transpose =====
    if (bid == 0 && tid == 0) { g_activeCount = 0; g_totalEntries = 0; }
    if (tid < UTOT) atomicMax(&g_owner[tp[tid]], ENCMAX - tid);
    __syncthreads();  // own marks complete -> owner values final (same set from all blocks)
    {
        int e = bid * EPB + tid;
        if (tid < EPB && e < NEDGES) {
            int s = ei[e], d = ei[NEDGES + e];
            int es = g_owner[s];
            if (es) {
                int u = ENCMAX - es;
                int p = atomicAdd(&g_degRaw[u], 1);
                if (p < DEGCAP) { g_rawEdge[u * DEGCAP + p] = e; g_rawNbr[u * DEGCAP + p] = d; }
            }
            if (s != d) {
                int ed = g_owner[d];
                if (ed) {
                    int u = ENCMAX - ed;
                    int p = atomicAdd(&g_degRaw[u], 1);
                    if (p < DEGCAP) { g_rawEdge[u * DEGCAP + p] = e; g_rawNbr[u * DEGCAP + p] = s; }
                }
            }
        }
    }
    for (int job = bid * 2 + half; job < 304; job += 2 * NB)
        transpose_job(job, &sX[half * 2048], htid, half,
                      inW, ftW, teW2, aiW, aoW, opW, o1W, o2W, l1W, l2W);
    gsync(gen);  // 1

    // ===== P1: sort (0..15) + prefix/odeg (16) + ensure_slot (17..) =====
    if (bid < 16) {
        int wid = tid >> 5, lane = tid & 31;
        int u = bid * 16 + wid;
        if (g_owner[tp[u]] == ENCMAX - u) {
            int d = min(g_degRaw[u], DEGCAP);
            int* sE = ((int*)sX) + wid * 128;
            int* sN = sE + 64;
            for (int i = lane; i < d; i += 32) {
                sE[i] = g_rawEdge[u * DEGCAP + i];
                sN[i] = g_rawNbr[u * DEGCAP + i];
            }
            __syncwarp();
            for (int i = lane; i < d; i += 32) {
                int key = sE[i], nb = sN[i], rank = 0;
                for (int j = 0; j < d; j++) rank += (sE[j] < key);
                g_srtEdge[u * DEGCAP + rank] = key;
                g_srtNbr[u * DEGCAP + rank] = nb;
            }
        }
    } else if (bid == 16) {
        int* lens = (int*)sX;
        int* excl = lens + 256;
        int* parts = excl + 256;
        int* poff = parts + 16;
        int lane = tid & 31, wid = tid >> 5;
        int u = tid;
        int own = 0, len = 0;
        if (tid < UTOT) {
            own = ENCMAX - g_owner[tp[u]];
            len = (own == u) ? min(g_degRaw[u], DEGCAP) : 0;
            lens[u] = len;
        }
        int v = len;
#pragma unroll
        for (int off = 1; off < 32; off <<= 1) {
            int n = __shfl_up_sync(0xffffffffu, v, off);
            if (lane >= off) v += n;
        }
        if (lane == 31 && wid < 8) parts[wid] = v;
        __syncthreads();
        if (tid == 0) {
            int a = 0;
            for (int w = 0; w < 8; w++) { poff[w] = a; a += parts[w]; }
            g_totalEntries = a;
        }
        __syncthreads();
        if (tid < UTOT) excl[u] = v - len + poff[wid];
        __syncthreads();
        if (tid < UTOT) {
            g_deg[u] = min(g_degRaw[own], DEGCAP);
            g_odeg[u] = len;
            g_incBase[u] = excl[own];
        }
    } else {
        for (int idx = (bid - 17) * NTHREADS + tid; idx < UTOT + MCAP;
             idx += (NB - 17) * NTHREADS) {
            if (idx < UTOT) {
                ensure_slot(tp[idx]);
            } else {
                int r = idx - UTOT;
                int u = r >> 6, i = r & 63;
                if (i < min(g_degRaw[u], DEGCAP)) ensure_slot(g_rawNbr[u * DEGCAP + i]);
            }
        }
    }
    gsync(gen);  // 2

    // ===== P2: compaction (last CPB) | fused x/tf0/tf1 tiles + tfeat tiles =====
    if (bid >= NB - CPB) {
        for (int idx = (bid - (NB - CPB)) * NTHREADS + tid; idx < UTOT + MCAP;
             idx += CPB * NTHREADS) {
            if (idx < UTOT) {
                g_tslot[idx] = g_node2slot[tp[idx]] - 1;
            } else {
                int r = idx - UTOT;
                int u = r >> 6, i = r & 63;
                if (g_owner[tp[u]] == ENCMAX - u && i < g_deg[u]) {
                    int b = g_incBase[u] + i;
                    g_entrySlot[b] = g_node2slot[g_srtNbr[u * DEGCAP + i]] - 1;
                    g_entryTIdx[b] = u * DEGCAP + i;
                }
            }
        }
    } else {
        int A = g_activeCount;
        int NTi = (A + TM - 1) / TM;
        int NW = NB - CPB;
        int J = NTi + 2 * UTOT * 8;
        for (int job = bid + unit * NW; job < J; job += UPB * NW) {
            float* Xs = sX + unit * (TM * HID);
            if (job < NTi) {
                float* Ys = sY + unit * (TM * HID);
                int r0 = job * TM;
                int nrows = min(TM, A - r0);
#pragma unroll
                for (int i = 0; i < TM; i++) {
                    float v = 0.f;
                    if (i < nrows) v = nf[(size_t)g_activeNodes[r0 + i] * HID + ut];
                    Xs[i * HID + ut] = v;
                }
                usync(unit);
                // x tile -> Ys + g_x
                {
                    float acc[TM];
#pragma unroll
                    for (int i = 0; i < TM; i++) acc[i] = 0.f;
                    const float4* X4 = reinterpret_cast<const float4*>(Xs);
                    const float* Wt = WT(0);
#pragma unroll 8
                    for (int k4 = 0; k4 < HID / 4; k4++) {
                        const float* wp = Wt + (k4 * 4) * HID + ut;
                        float w0 = wp[0], w1 = wp[HID], w2 = wp[2 * HID], w3 = wp[3 * HID];
#pragma unroll
                        for (int i = 0; i < TM; i++) {
                            float4 x = X4[i * (HID / 4) + k4];
                            acc[i] += x.x * w0 + x.y * w1 + x.z * w2 + x.w * w3;
                        }
                    }
                    float bb = inb[ut];
#pragma unroll
                    for (int i = 0; i < TM; i++) {
                        float v = acc[i] + bb;
                        Ys[i * HID + ut] = v;
                        if (i < nrows) g_x[(size_t)(r0 + i) * HID + ut] = v;
                    }
                }
                usync(unit);
                tile_compute(Ys, nrows, WT(1), ftb, g_tf, r0, ut);
                tile_compute_relu(Ys, nrows, WT(2), ftb + HID, g_tf + TFS, r0, ut);
            } else {
                int j = job - NTi;
                int l = j >> 11;
                int u = (j >> 3) & 255;
                int c = j & 7;
                int od = g_odeg[u];
                int r0 = c * TM;
                if (r0 >= od) continue;
                int nrows = min(TM, od - r0);
                float w1 = teW1[l * HID + ut], b1 = teb1[l * HID + ut];
#pragma unroll
                for (int i = 0; i < TM; i++) {
                    float v = 0.f;
                    if (i < nrows)
                        v = fmaxf(ets[g_srtEdge[u * DEGCAP + r0 + i]] * w1 + b1, 0.f);
                    Xs[i * HID + ut] = v;
                }
                usync(unit);
                tile_compute(Xs, nrows, WT(3 + l), teb2 + l * HID,
                             g_tfeat + (size_t)(l * MCAP + u * DEGCAP) * HID, r0, ut);
            }
            usync(unit);
        }
    }
    gsync(gen);  // 3

    // ===== layers: B (K/V/q), C (attention + projections, tf1 patch on l=0) =====
    for (int l = 0; l < 2; l++) {
        int M = g_totalEntries;
        int NE = (M + TM - 1) / TM;
        const float* bq = aib + (size_t)l * 3 * HID;
        const float* bk = bq + HID;
        const float* bv = bq + 2 * HID;
        const float* bo = aob + l * HID;
        const float* bop = opb + l * HID;
        const float* tfl = g_tf + (size_t)l * TFS;

        // ---- B: K+V merged (entries) + q (targets) ----
        int NQ = UTOT / TM;
        for (int job = bid + unit * NB; job < NE + NQ; job += NUNITS) {
            float* Xs = sX + unit * (TM * HID);
            if (job < NE) {
                int r0 = job * TM;
                int nrows = min(TM, M - r0);
#pragma unroll
                for (int i = 0; i < TM; i++) {
                    float v = 0.f;
                    if (i < nrows) {
                        int r = r0 + i;
                        v = tfl[(size_t)g_entrySlot[r] * HID + ut] +
                            g_tfeat[(size_t)(l * MCAP + g_entryTIdx[r]) * HID + ut];
                    }
                    Xs[i * HID + ut] = v;
                }
                usync(unit);
                tile_compute(Xs, nrows, WT(7 + l), bk, g_K, r0, ut);
                tile_compute(Xs, nrows, WT(9 + l), bv, g_V, r0, ut);
            } else {
                int r0 = (job - NE) * TM;
#pragma unroll
                for (int i = 0; i < TM; i++)
                    Xs[i * HID + ut] = tfl[(size_t)g_tslot[r0 + i] * HID + ut];
                usync(unit);
                tile_compute(Xs, TM, WT(5 + l), bq, g_q, r0, ut);
            }
            usync(unit);
        }
        gsync(gen);  // 4, 6

        // ---- C: attention + out/op projection (+ tf1 patch when l==0) ----
        for (int u = bid + unit * NB; u < UTOT; u += NUNITS) {
            float* sc = sAux + unit * 768;  // [4][64]
            float* sq = sc + 256;           // 128
            float* vec = sc + 384;          // 128
            float* sout = sc + 512;         // 128
            int lane = ut & 31, h = ut >> 5;
            int deg = g_deg[u];
            int base = g_incBase[u];
            int slot = g_tslot[u];
            if (deg > 0) {
                sq[ut] = g_q[u * HID + ut];
                usync(unit);
                int ih = ut & 3, ii = ut >> 2;
#pragma unroll 2
                for (int p0 = 0; p0 < DEGCAP; p0 += 32) {
                    int i = p0 + ii;
                    if (i < deg) {
                        const float4* Kp = reinterpret_cast<const float4*>(
                            g_K + (size_t)(base + i) * HID + ih * 32);
                        const float4* qp = reinterpret_cast<const float4*>(sq + ih * 32);
                        float a = 0.f;
#pragma unroll
                        for (int k = 0; k < 8; k++) {
                            float4 kv = Kp[k];
                            float4 qv = qp[k];
                            a += kv.x * qv.x + kv.y * qv.y + kv.z * qv.z + kv.w * qv.w;
                        }
                        sc[ih * 64 + i] = a * SCALE;
                    }
                    if (p0 + 32 >= deg) break;
                }
                usync(unit);
                float mx = -1e30f;
                for (int i = lane; i < deg; i += 32) mx = fmaxf(mx, sc[h * 64 + i]);
#pragma unroll
                for (int o = 16; o > 0; o >>= 1)
                    mx = fmaxf(mx, __shfl_xor_sync(0xffffffffu, mx, o));
                float ssum = 0.f;
                for (int i = lane; i < deg; i += 32) {
                    float p = expf(sc[h * 64 + i] - mx);
                    sc[h * 64 + i] = p;
                    ssum += p;
                }
#pragma unroll
                for (int o = 16; o > 0; o >>= 1)
                    ssum += __shfl_xor_sync(0xffffffffu, ssum, o);
                float inv = 1.f / ssum;
                __syncwarp();
                float oacc = 0.f;
#pragma unroll 4
                for (int i = 0; i < deg; i++)
                    oacc += sc[h * 64 + i] * inv * g_V[(size_t)(base + i) * HID + ut];
                vec[ut] = oacc;
                usync(unit);
                float at = gemv128(vec, WT(11 + l), ut) + bo[ut];
                usync(unit);
                sout[ut] = at;
            } else {
                sout[ut] = tfl[(size_t)slot * HID + ut];
            }
            usync(unit);
            float nx = gemv128(sout, WT(13 + l), ut) + bop[ut];
            g_x[(size_t)slot * HID + ut] = nx;
            if (l == 0) {  // patch this target's tf1 row (same unit, no grid sync)
                usync(unit);
                sout[ut] = fmaxf(nx, 0.f);
                usync(unit);
                float t1 = gemv128(sout, WT(2), ut) + ftb[HID + ut];
                g_tf[TFS + (size_t)slot * HID + ut] = t1;
            }
            usync(unit);
        }
        gsync(gen);  // 5, 7
    }

    // ===== head + cleanup =====
    for (int p = bid + unit * NB; p < NPAIRS; p += NUNITS) {
        float* sx = sX + unit * (TM * HID);
        float* shh = sx + 128;
        float* pair = sx + 256;
        float* zz = sx + 384;
        float* z2 = sx + 512;
        for (int side = 0; side < 2; side++) {
            int slot = g_tslot[2 * p + side];
            sx[ut] = fmaxf(g_x[(size_t)slot * HID + ut], 0.f);
            usync(unit);
            float hv = fmaxf(gemv128(sx, WT(15), ut) + o1b[ut], 0.f);
            usync(unit);
            shh[ut] = hv;
            usync(unit);
            if (ut < OUTD) {
                const float* W2t = WT(16);
                float a2 = 0.f;
#pragma unroll 8
                for (int k = 0; k < HID; k++) a2 += shh[k] * W2t[k * OUTD + ut];
                pair[side * OUTD + ut] = a2 + o2b[ut];
            }
            usync(unit);
        }
        {
            const float* Wt = WT(17);
            float acc = 0.f;
#pragma unroll 8
            for (int k = 0; k < 2 * OUTD; k++) acc += pair[k] * Wt[k * HID + ut];
            zz[ut] = fmaxf(acc + l1b[ut], 0.f);
        }
        usync(unit);
        if (ut < OUTD) {
            const float* Wt = WT(18);
            float a = 0.f;
#pragma unroll 8
            for (int k = 0; k < HID; k++) a += zz[k] * Wt[k * OUTD + ut];
            z2[ut] = fmaxf(a + l2b[ut], 0.f);
        }
        usync(unit);
        if (ut == 0) {
            float a = 0.f;
            for (int k = 0; k < OUTD; k++) a += z2[k] * l3W[k];
            a += l3b[0];
            out[p] = 1.f / (1.f + expf(-a));
        }
        usync(unit);
    }
    // cleanup: restore zero-init sentinels (scalars reset next replay in P0)
    {
        int A = g_activeCount;
        for (int idx = bid * NTHREADS + tid; idx < A + UTOT; idx += NB * NTHREADS) {
            if (idx < A) {
                g_node2slot[g_activeNodes[idx]] = 0;
            } else {
                int u = idx - A;
                g_owner[tp[u]] = 0;
                g_degRaw[u] = 0;
            }
        }
    }
}

// ---------------- launch ----------------
extern "C" void kernel_launch(void* const* d_in, const int* in_sizes, int n_in,
                              void* d_out, int out_size) {
    const float* nf    = (const float*)d_in[0];
    const int*   ei    = (const int*)d_in[1];
    const float* ets   = (const float*)d_in[2];
    const int*   tp    = (const int*)d_in[3];
    const float* in_W  = (const float*)d_in[4];
    const float* in_b  = (const float*)d_in[5];
    const float* te_W1 = (const float*)d_in[6];
    const float* te_b1 = (const float*)d_in[7];
    const float* te_W2 = (const float*)d_in[8];
    const float* te_b2 = (const float*)d_in[9];
    const float* aiW   = (const float*)d_in[10];
    const float* aib   = (const float*)d_in[11];
    const float* aoW   = (const float*)d_in[12];
    const float* aob   = (const float*)d_in[13];
    const float* ftW   = (const float*)d_in[14];
    const float* ftb   = (const float*)d_in[15];
    const float* opW   = (const float*)d_in[16];
    const float* opb   = (const float*)d_in[17];
    const float* o1W   = (const float*)d_in[18];
    const float* o1b   = (const float*)d_in[19];
    const float* o2W   = (const float*)d_in[20];
    const float* o2b   = (const float*)d_in[21];
    const float* l1W   = (const float*)d_in[22];
    const float* l1b   = (const float*)d_in[23];
    const float* l2W   = (const float*)d_in[24];
    const float* l2b   = (const float*)d_in[25];
    const float* l3W   = (const float*)d_in[26];
    const float* l3b   = (const float*)d_in[27];
    float* out = (float*)d_out;

    k_main<<<NB, NTHREADS>>>(nf, ei, ets, tp, in_W, in_b, te_W1, te_b1, te_W2, te_b2,
                             aiW, aib, aoW, aob, ftW, ftb, opW, opb,
                             o1W, o1b, o2W, o2b, l1W, l1b, l2W, l2b, l3W, l3b, out);
}

// round 16
// speedup vs baseline: 1.2362x; 1.2362x over previous
#include <cuda_runtime.h>
#include <math.h>

#define NNODES 20000
#define NEDGES 50000
#define HID 128
#define OUTD 64
#define NPAIRS 128
#define UTOT 256
#define DEGCAP 64
#define MCAP (UTOT * DEGCAP)   /* 16384 */
#define ACAPN (UTOT + MCAP)    /* 16640 */
#define TM 8
#define NB 148
#define NTHREADS 512
#define UPB 4
#define NUNITS (UPB * NB)      /* 592 */
#define CPB 8
#define GRP 4
#define GSZ 37
#define EPB 338                /* 148*338 >= 50000 */
#define ENCMAX 0x7fffffff
#define SCALE 0.17677669529663687f

// ---------------- device scratch (zero-init == clean state) ----------------
__device__ int g_owner[NNODES];      // 0 = unmarked, else ENCMAX - u
__device__ int g_node2slot[NNODES];  // 0 = none, -1 = lock, else slot+1
__device__ int g_degRaw[UTOT];
__device__ int g_rawEdge[MCAP];
__device__ int g_rawNbr[MCAP];
__device__ int g_srtEdge[MCAP];
__device__ int g_srtNbr[MCAP];
__device__ int g_deg[UTOT];
__device__ int g_incBase[UTOT];
__device__ int g_tslot[UTOT];
__device__ int g_entryEdge[MCAP];
__device__ int g_entrySlot[MCAP];
__device__ int g_activeNodes[ACAPN];
__device__ int g_activeCount;
__device__ int g_totalEntries;
// tree barrier: per-group arrive counters (separate lines), root, published gen
__device__ __align__(128) unsigned g_grpArr[GRP * 32];
__device__ __align__(128) unsigned g_rootArr[32];
__device__ __align__(128) unsigned g_genPub[32];

__device__ float g_x[ACAPN * HID];
__device__ float g_tf[ACAPN * HID];
__device__ float g_tfeat[MCAP * HID];
__device__ float g_K[MCAP * HID];
__device__ float g_V[MCAP * HID];
__device__ float g_q[UTOT * HID];
__device__ float g_bc[2][HID];       // combined ao->op bias per layer
__device__ float g_WT[21 * HID * HID];
// transposed: 0:in 1,2:ft 3,4:te2 5,6:q 7,8:k 9,10:v 11,12:ao 13,14:op
// 15:o1 16:o2(R=64) 17:l1 18:l2(R=64) 19,20: combined (Wop*Wao)^T per layer

__device__ __forceinline__ const float* WT(int m) { return g_WT + m * HID * HID; }

// ---- two-level tree barrier: group atomics in parallel, one-hop release ----
__device__ __forceinline__ void gsync(unsigned& gen) {
    __syncthreads();
    if (threadIdx.x == 0) {
        gen++;
        int g = blockIdx.x & (GRP - 1);
        unsigned old;
        asm volatile("atom.add.release.gpu.u32 %0, [%1], 1;"
                     : "=r"(old) : "l"(&g_grpArr[g * 32]) : "memory");
        if (old == gen * GSZ - 1u) {
            unsigned ro;
            asm volatile("atom.add.release.gpu.u32 %0, [%1], 1;"
                         : "=r"(ro) : "l"(&g_rootArr[0]) : "memory");
            if (ro == gen * GRP - 1u) {
                __threadfence();
                asm volatile("st.release.gpu.u32 [%0], %1;"
                             ::"l"(&g_genPub[0]), "r"(gen) : "memory");
            }
        }
        unsigned v;
        do {
            asm volatile("ld.acquire.gpu.u32 %0, [%1];"
                         : "=r"(v) : "l"(&g_genPub[0]) : "memory");
        } while (v < gen);
    }
    __syncthreads();
}

__device__ __forceinline__ void usync(int unit) {
    asm volatile("bar.sync %0, 128;" ::"r"(unit + 1) : "memory");
}
__device__ __forceinline__ void hsync(int half) {
    asm volatile("bar.sync %0, 256;" ::"r"(half + 5) : "memory");
}

__device__ __forceinline__ void ensure_slot(int n) {
    if (g_node2slot[n] == 0) {
        if (atomicCAS(&g_node2slot[n], 0, -1) == 0) {
            int s = atomicAdd(&g_activeCount, 1);
            g_activeNodes[s] = n;
            __threadfence();
            g_node2slot[n] = s + 1;
        }
    }
}

// one 128x32 transpose tile job
__device__ __forceinline__ void transpose_job(
    int job, float* sh, int htid, int half,
    const float* inW, const float* ftW, const float* teW2, const float* aiW,
    const float* aoW, const float* opW, const float* o1W, const float* o2W,
    const float* l1W, const float* l2W) {
    int m = job >> 4, t = job & 15;
    const float* src;
    int R = HID;
    switch (m) {
        case 0: src = inW; break;
        case 1: case 2: src = ftW + (size_t)(m - 1) * HID * HID; break;
        case 3: case 4: src = teW2 + (size_t)(m - 3) * HID * HID; break;
        case 5: case 6: src = aiW + (size_t)(m - 5) * 3 * HID * HID; break;
        case 7: case 8: src = aiW + (size_t)(m - 7) * 3 * HID * HID + HID * HID; break;
        case 9: case 10: src = aiW + (size_t)(m - 9) * 3 * HID * HID + 2 * HID * HID; break;
        case 11: case 12: src = aoW + (size_t)(m - 11) * HID * HID; break;
        case 13: case 14: src = opW + (size_t)(m - 13) * HID * HID; break;
        case 15: src = o1W; break;
        case 16: src = o2W; R = OUTD; break;
        case 17: src = l1W; break;
        default: src = l2W; R = OUTD; break;
    }
    int tr = t >> 2, tc = t & 3;
    if (tr * 32 >= R) return;
    int x = htid & 31, y0 = htid >> 5;
    float* dst = g_WT + (size_t)m * HID * HID;
#pragma unroll
    for (int k = 0; k < 4; k++) {
        int y = y0 + 8 * k;
        sh[y * 33 + x] = src[(size_t)(tr * 32 + y) * HID + tc * 32 + x];
    }
    hsync(half);
#pragma unroll
    for (int k = 0; k < 4; k++) {
        int y = y0 + 8 * k;
        dst[(size_t)(tc * 32 + y) * R + tr * 32 + x] = sh[x * 33 + y];
    }
    hsync(half);
}

// Xs: TM x HID shared; Wt: [k][o]; out rows
__device__ __forceinline__ void tile_compute(const float* Xs, int nrows,
                                             const float* __restrict__ Wt,
                                             const float* __restrict__ b,
                                             float* __restrict__ out, int row0, int ut) {
    float acc[TM];
#pragma unroll
    for (int i = 0; i < TM; i++) acc[i] = 0.f;
    const float4* X4 = reinterpret_cast<const float4*>(Xs);
#pragma unroll 8
    for (int k4 = 0; k4 < HID / 4; k4++) {
        const float* wp = Wt + (k4 * 4) * HID + ut;
        float w0 = wp[0];
        float w1 = wp[HID];
        float w2 = wp[2 * HID];
        float w3 = wp[3 * HID];
#pragma unroll
        for (int i = 0; i < TM; i++) {
            float4 x = X4[i * (HID / 4) + k4];
            acc[i] += x.x * w0 + x.y * w1 + x.z * w2 + x.w * w3;
        }
    }
    float bb = b ? b[ut] : 0.f;
    for (int i = 0; i < nrows; i++) out[(size_t)(row0 + i) * HID + ut] = acc[i] + bb;
}

// shared x [128] dot columns of Wt -> one output per thread
__device__ __forceinline__ float gemv128(const float* xs, const float* __restrict__ Wt,
                                         int ut) {
    float a0 = 0.f, a1 = 0.f, a2 = 0.f, a3 = 0.f;
#pragma unroll 4
    for (int k = 0; k < HID; k += 4) {
        a0 += xs[k] * Wt[k * HID + ut];
        a1 += xs[k + 1] * Wt[(k + 1) * HID + ut];
        a2 += xs[k + 2] * Wt[(k + 2) * HID + ut];
        a3 += xs[k + 3] * Wt[(k + 3) * HID + ut];
    }
    return (a0 + a1) + (a2 + a3);
}

// dual gemv: two inputs share each weight load
__device__ __forceinline__ void gemv128x2(const float* xa, const float* xb,
                                          const float* __restrict__ Wt, int ut,
                                          float& ra, float& rb) {
    float a0 = 0.f, a1 = 0.f, b0 = 0.f, b1 = 0.f;
#pragma unroll 4
    for (int k = 0; k < HID; k += 2) {
        float w0 = Wt[k * HID + ut];
        float w1 = Wt[(k + 1) * HID + ut];
        a0 += xa[k] * w0; a1 += xa[k + 1] * w1;
        b0 += xb[k] * w0; b1 += xb[k + 1] * w1;
    }
    ra = a0 + a1;
    rb = b0 + b1;
}

__global__ __launch_bounds__(NTHREADS, 1) void k_main(
    const float* __restrict__ nf, const int* __restrict__ ei,
    const float* __restrict__ ets, const int* __restrict__ tp,
    const float* __restrict__ inW, const float* __restrict__ inb,
    const float* __restrict__ teW1, const float* __restrict__ teb1,
    const float* __restrict__ teW2, const float* __restrict__ teb2,
    const float* __restrict__ aiW, const float* __restrict__ aib,
    const float* __restrict__ aoW, const float* __restrict__ aob,
    const float* __restrict__ ftW, const float* __restrict__ ftb,
    const float* __restrict__ opW, const float* __restrict__ opb,
    const float* __restrict__ o1W, const float* __restrict__ o1b,
    const float* __restrict__ o2W, const float* __restrict__ o2b,
    const float* __restrict__ l1W, const float* __restrict__ l1b,
    const float* __restrict__ l2W, const float* __restrict__ l2b,
    const float* __restrict__ l3W, const float* __restrict__ l3b,
    float* __restrict__ out) {
    __shared__ __align__(16) float sX[UPB * TM * HID];  // 16KB
    __shared__ __align__(16) float sAux[UPB * 768];     // 12KB
    int tid = threadIdx.x;
    int unit = tid >> 7;
    int ut = tid & 127;
    int half = tid >> 8;
    int htid = tid & 255;
    int bid = blockIdx.x;
    unsigned gen;
    {
        unsigned v;
        asm volatile("ld.acquire.gpu.u32 %0, [%1];"
                     : "=r"(v) : "l"(&g_genPub[0]) : "memory");
        gen = v;
    }

    // ===== P0: redundant mark + private edge scan + ALL weight transposes =====
    if (bid == 0 && tid == 0) { g_activeCount = 0; g_totalEntries = 0; }
    if (tid < UTOT) atomicMax(&g_owner[tp[tid]], ENCMAX - tid);
    __syncthreads();  // this block's marks done -> owner values are final
    {
        int e = bid * EPB + tid;
        if (tid < EPB && e < NEDGES) {
            int s = ei[e], d = ei[NEDGES + e];
            int es = g_owner[s];
            if (es) {
                int u = ENCMAX - es;
                int p = atomicAdd(&g_degRaw[u], 1);
                if (p < DEGCAP) { g_rawEdge[u * DEGCAP + p] = e; g_rawNbr[u * DEGCAP + p] = d; }
            }
            if (s != d) {
                int ed = g_owner[d];
                if (ed) {
                    int u = ENCMAX - ed;
                    int p = atomicAdd(&g_degRaw[u], 1);
                    if (p < DEGCAP) { g_rawEdge[u * DEGCAP + p] = e; g_rawNbr[u * DEGCAP + p] = s; }
                }
            }
        }
    }
    for (int job = bid * 2 + half; job < 304; job += 2 * NB)
        transpose_job(job, &sX[half * 2048], htid, half,
                      inW, ftW, teW2, aiW, aoW, opW, o1W, o2W, l1W, l2W);
    gsync(gen);  // 1

    // ===== P1: sort (0..15) + prefix (16) + slots (17..99) + combo mats (100..) =====
    if (bid < 16) {
        int wid = tid >> 5, lane = tid & 31;
        int u = bid * 16 + wid;
        if (g_owner[tp[u]] == ENCMAX - u) {
            int d = min(g_degRaw[u], DEGCAP);
            int* sE = ((int*)sX) + wid * 128;
            int* sN = sE + 64;
            for (int i = lane; i < d; i += 32) {
                sE[i] = g_rawEdge[u * DEGCAP + i];
                sN[i] = g_rawNbr[u * DEGCAP + i];
            }
            __syncwarp();
            for (int i = lane; i < d; i += 32) {
                int key = sE[i], nb = sN[i], rank = 0;
                for (int j = 0; j < d; j++) rank += (sE[j] < key);
                g_srtEdge[u * DEGCAP + rank] = key;
                g_srtNbr[u * DEGCAP + rank] = nb;
            }
        }
    } else if (bid == 16) {
        int* lens = (int*)sX;
        int* excl = lens + 256;
        int* parts = excl + 256;
        int* poff = parts + 16;
        int lane = tid & 31, wid = tid >> 5;
        int u = tid;
        int own = 0, len = 0;
        if (tid < UTOT) {
            own = ENCMAX - g_owner[tp[u]];
            len = (own == u) ? min(g_degRaw[u], DEGCAP) : 0;
            lens[u] = len;
        }
        int v = len;
#pragma unroll
        for (int off = 1; off < 32; off <<= 1) {
            int n = __shfl_up_sync(0xffffffffu, v, off);
            if (lane >= off) v += n;
        }
        if (lane == 31 && wid < 8) parts[wid] = v;
        __syncthreads();
        if (tid == 0) {
            int a = 0;
            for (int w = 0; w < 8; w++) { poff[w] = a; a += parts[w]; }
            g_totalEntries = a;
        }
        __syncthreads();
        if (tid < UTOT) excl[u] = v - len + poff[wid];
        __syncthreads();
        if (tid < UTOT) {
            g_deg[u] = min(g_degRaw[own], DEGCAP);
            g_incBase[u] = excl[own];
        }
    } else if (bid < 100) {
        for (int idx = (bid - 17) * NTHREADS + tid; idx < UTOT + MCAP;
             idx += 83 * NTHREADS) {
            if (idx < UTOT) {
                ensure_slot(tp[idx]);
            } else {
                int r = idx - UTOT;
                int u = r >> 6, i = r & 63;
                if (i < min(g_degRaw[u], DEGCAP)) ensure_slot(g_rawNbr[u * DEGCAP + i]);
            }
        }
    } else {
        // combined matrices: CT_l = WT(11+l) x WT(13+l) -> WT(19+l); bias -> g_bc[l]
        int job = (bid - 100) * UPB + unit;
        float* Xs = sX + unit * (TM * HID);
        if (job < 32) {
            int l = job >> 4;
            int t = job & 15;
            int r0 = t * TM;
            const float* src = WT(11 + l);
#pragma unroll
            for (int i = 0; i < TM; i++)
                Xs[i * HID + ut] = src[(size_t)(r0 + i) * HID + ut];
            usync(unit);
            tile_compute(Xs, TM, WT(13 + l), nullptr, g_WT + (size_t)(19 + l) * HID * HID,
                         r0, ut);
        } else if (job < 34) {
            int l = job - 32;
            Xs[ut] = aob[l * HID + ut];
            usync(unit);
            g_bc[l][ut] = gemv128(Xs, WT(13 + l), ut) + opb[l * HID + ut];
        }
    }
    gsync(gen);  // 2

    // ===== P2: compaction (last CPB blocks) | input projection (rest) =====
    if (bid >= NB - CPB) {
        for (int idx = (bid - (NB - CPB)) * NTHREADS + tid; idx < UTOT + MCAP;
             idx += CPB * NTHREADS) {
            if (idx < UTOT) {
                g_tslot[idx] = g_node2slot[tp[idx]] - 1;
            } else {
                int r = idx - UTOT;
                int u = r >> 6, i = r & 63;
                if (g_owner[tp[u]] == ENCMAX - u && i < g_deg[u]) {
                    int b = g_incBase[u] + i;
                    g_entryEdge[b] = g_srtEdge[u * DEGCAP + i];
                    g_entrySlot[b] = g_node2slot[g_srtNbr[u * DEGCAP + i]] - 1;
                }
            }
        }
    } else {
        int A = g_activeCount;
        int NTi = (A + TM - 1) / TM;
        int NW = NB - CPB;
        for (int uid = bid + unit * NW; uid < NTi; uid += UPB * NW) {
            int r0 = uid * TM;
            int nrows = min(TM, A - r0);
            float* Xs = sX + unit * (TM * HID);
#pragma unroll
            for (int i = 0; i < TM; i++) {
                float v = 0.f;
                if (i < nrows) v = nf[(size_t)g_activeNodes[r0 + i] * HID + ut];
                Xs[i * HID + ut] = v;
            }
            usync(unit);
            tile_compute(Xs, nrows, WT(0), inb, g_x, r0, ut);
            usync(unit);
        }
    }
    gsync(gen);  // 3

    // ===== layers: A (tf + tfeat), B (K/V/q), C (attention) =====
    for (int l = 0; l < 2; l++) {
        int A = g_activeCount, M = g_totalEntries;
        int NT = (A + TM - 1) / TM, NE = (M + TM - 1) / TM;
        const float* teW1l = teW1 + l * HID;
        const float* teb1l = teb1 + l * HID;
        const float* teb2l = teb2 + l * HID;
        const float* ftbl = ftb + l * HID;
        const float* bq = aib + (size_t)l * 3 * HID;
        const float* bk = bq + HID;
        const float* bv = bq + 2 * HID;
        const float* bop = opb + l * HID;

        // ---- A: tf (actives) + tfeat (compacted entries) ----
        for (int job = bid + unit * NB; job < NT + NE; job += NUNITS) {
            float* Xs = sX + unit * (TM * HID);
            if (job < NT) {
                int r0 = job * TM;
                int nrows = min(TM, A - r0);
#pragma unroll
                for (int i = 0; i < TM; i++) {
                    float v = 0.f;
                    if (i < nrows) v = g_x[(size_t)(r0 + i) * HID + ut];
                    if (l) v = fmaxf(v, 0.f);
                    Xs[i * HID + ut] = v;
                }
                usync(unit);
                tile_compute(Xs, nrows, WT(1 + l), ftbl, g_tf, r0, ut);
            } else {
                int r0 = (job - NT) * TM;
                int nrows = min(TM, M - r0);
                float w1 = teW1l[ut], b1 = teb1l[ut];
#pragma unroll
                for (int i = 0; i < TM; i++) {
                    float v = 0.f;
                    if (i < nrows) v = fmaxf(ets[g_entryEdge[r0 + i]] * w1 + b1, 0.f);
                    Xs[i * HID + ut] = v;
                }
                usync(unit);
                tile_compute(Xs, nrows, WT(3 + l), teb2l, g_tfeat, r0, ut);
            }
            usync(unit);
        }
        gsync(gen);  // 4, 7

        // ---- B: K+V merged (entries) + q (targets) ----
        int NQ = UTOT / TM;
        for (int job = bid + unit * NB; job < NE + NQ; job += NUNITS) {
            float* Xs = sX + unit * (TM * HID);
            if (job < NE) {
                int r0 = job * TM;
                int nrows = min(TM, M - r0);
#pragma unroll
                for (int i = 0; i < TM; i++) {
                    float v = 0.f;
                    if (i < nrows) {
                        int r = r0 + i;
                        v = g_tf[(size_t)g_entrySlot[r] * HID + ut] +
                            g_tfeat[(size_t)r * HID + ut];
                    }
                    Xs[i * HID + ut] = v;
                }
                usync(unit);
                tile_compute(Xs, nrows, WT(7 + l), bk, g_K, r0, ut);
                tile_compute(Xs, nrows, WT(9 + l), bv, g_V, r0, ut);
            } else {
                int r0 = (job - NE) * TM;
#pragma unroll
                for (int i = 0; i < TM; i++)
                    Xs[i * HID + ut] = g_tf[(size_t)g_tslot[r0 + i] * HID + ut];
                usync(unit);
                tile_compute(Xs, TM, WT(5 + l), bq, g_q, r0, ut);
            }
            usync(unit);
        }
        gsync(gen);  // 5, 8

        // ---- C: attention + combined ao∘op projection ----
        for (int u = bid + unit * NB; u < UTOT; u += NUNITS) {
            float* sc = sAux + unit * 768;  // [4][64]
            float* sq = sc + 256;           // 128
            float* vec = sc + 384;          // 128
            float* sout = sc + 512;         // 128
            int lane = ut & 31, h = ut >> 5;
            int deg = g_deg[u];
            int base = g_incBase[u];
            int slot = g_tslot[u];
            float nx;
            if (deg > 0) {
                sq[ut] = g_q[u * HID + ut];
                usync(unit);
                int ih = ut & 3, ii = ut >> 2;
#pragma unroll 2
                for (int p0 = 0; p0 < DEGCAP; p0 += 32) {
                    int i = p0 + ii;
                    if (i < deg) {
                        const float4* Kp = reinterpret_cast<const float4*>(
                            g_K + (size_t)(base + i) * HID + ih * 32);
                        const float4* qp = reinterpret_cast<const float4*>(sq + ih * 32);
                        float a = 0.f;
#pragma unroll
                        for (int k = 0; k < 8; k++) {
                            float4 kv = Kp[k];
                            float4 qv = qp[k];
                            a += kv.x * qv.x + kv.y * qv.y + kv.z * qv.z + kv.w * qv.w;
                        }
                        sc[ih * 64 + i] = a * SCALE;
                    }
                    if (p0 + 32 >= deg) break;
                }
                usync(unit);
                float mx = -1e30f;
                for (int i = lane; i < deg; i += 32) mx = fmaxf(mx, sc[h * 64 + i]);
#pragma unroll
                for (int o = 16; o > 0; o >>= 1)
                    mx = fmaxf(mx, __shfl_xor_sync(0xffffffffu, mx, o));
                float ssum = 0.f;
                for (int i = lane; i < deg; i += 32) {
                    float p = expf(sc[h * 64 + i] - mx);
                    sc[h * 64 + i] = p;
                    ssum += p;
                }
#pragma unroll
                for (int o = 16; o > 0; o >>= 1)
                    ssum += __shfl_xor_sync(0xffffffffu, ssum, o);
                float inv = 1.f / ssum;
                __syncwarp();
                float oacc = 0.f;
#pragma unroll 4
                for (int i = 0; i < deg; i++)
                    oacc += sc[h * 64 + i] * inv * g_V[(size_t)(base + i) * HID + ut];
                vec[ut] = oacc;
                usync(unit);
                nx = gemv128(vec, WT(19 + l), ut) + g_bc[l][ut];
            } else {
                sout[ut] = g_tf[(size_t)slot * HID + ut];
                usync(unit);
                nx = gemv128(sout, WT(13 + l), ut) + bop[ut];
            }
            g_x[(size_t)slot * HID + ut] = nx;
            usync(unit);
        }
        gsync(gen);  // 6, 9
    }

    // ===== head (dual-side gemvs) + cleanup =====
    for (int p = bid + unit * NB; p < NPAIRS; p += NUNITS) {
        float* sx0 = sX + unit * (TM * HID);
        float* sx1 = sx0 + 128;
        float* sh0 = sx0 + 256;
        float* sh1 = sx0 + 384;
        float* pair = sx0 + 512;
        float* zz = sx0 + 640;
        float* z2 = sx0 + 768;
        sx0[ut] = fmaxf(g_x[(size_t)g_tslot[2 * p] * HID + ut], 0.f);
        sx1[ut] = fmaxf(g_x[(size_t)g_tslot[2 * p + 1] * HID + ut], 0.f);
        usync(unit);
        float h0, h1;
        gemv128x2(sx0, sx1, WT(15), ut, h0, h1);
        float b1v = o1b[ut];
        h0 = fmaxf(h0 + b1v, 0.f);
        h1 = fmaxf(h1 + b1v, 0.f);
        usync(unit);
        sh0[ut] = h0;
        sh1[ut] = h1;
        usync(unit);
        if (ut < OUTD) {
            const float* W2t = WT(16);
            float a0 = 0.f, a1 = 0.f;
#pragma unroll 8
            for (int k = 0; k < HID; k++) {
                float w = W2t[k * OUTD + ut];
                a0 += sh0[k] * w;
                a1 += sh1[k] * w;
            }
            float b2v = o2b[ut];
            pair[ut] = a0 + b2v;
            pair[OUTD + ut] = a1 + b2v;
        }
        usync(unit);
        {
            const float* Wt = WT(17);
            float acc = 0.f;
#pragma unroll 8
            for (int k = 0; k < 2 * OUTD; k++) acc += pair[k] * Wt[k * HID + ut];
            zz[ut] = fmaxf(acc + l1b[ut], 0.f);
        }
        usync(unit);
        if (ut < OUTD) {
            const float* Wt = WT(18);
            float a = 0.f;
#pragma unroll 8
            for (int k = 0; k < HID; k++) a += zz[k] * Wt[k * OUTD + ut];
            z2[ut] = fmaxf(a + l2b[ut], 0.f);
        }
        usync(unit);
        if (ut == 0) {
            float a = 0.f;
            for (int k = 0; k < OUTD; k++) a += z2[k] * l3W[k];
            a += l3b[0];
            out[p] = 1.f / (1.f + expf(-a));
        }
        usync(unit);
    }
    // cleanup: restore zero-init sentinels (scalars reset next replay in P0)
    {
        int A = g_activeCount;
        for (int idx = bid * NTHREADS + tid; idx < A + UTOT; idx += NB * NTHREADS) {
            if (idx < A) {
                g_node2slot[g_activeNodes[idx]] = 0;
            } else {
                int u = idx - A;
                g_owner[tp[u]] = 0;
                g_degRaw[u] = 0;
            }
        }
    }
}

// ---------------- launch ----------------
extern "C" void kernel_launch(void* const* d_in, const int* in_sizes, int n_in,
                              void* d_out, int out_size) {
    const float* nf    = (const float*)d_in[0];
    const int*   ei    = (const int*)d_in[1];
    const float* ets   = (const float*)d_in[2];
    const int*   tp    = (const int*)d_in[3];
    const float* in_W  = (const float*)d_in[4];
    const float* in_b  = (const float*)d_in[5];
    const float* te_W1 = (const float*)d_in[6];
    const float* te_b1 = (const float*)d_in[7];
    const float* te_W2 = (const float*)d_in[8];
    const float* te_b2 = (const float*)d_in[9];
    const float* aiW   = (const float*)d_in[10];
    const float* aib   = (const float*)d_in[11];
    const float* aoW   = (const float*)d_in[12];
    const float* aob   = (const float*)d_in[13];
    const float* ftW   = (const float*)d_in[14];
    const float* ftb   = (const float*)d_in[15];
    const float* opW   = (const float*)d_in[16];
    const float* opb   = (const float*)d_in[17];
    const float* o1W   = (const float*)d_in[18];
    const float* o1b   = (const float*)d_in[19];
    const float* o2W   = (const float*)d_in[20];
    const float* o2b   = (const float*)d_in[21];
    const float* l1W   = (const float*)d_in[22];
    const float* l1b   = (const float*)d_in[23];
    const float* l2W   = (const float*)d_in[24];
    const float* l2b   = (const float*)d_in[25];
    const float* l3W   = (const float*)d_in[26];
    const float* l3b   = (const float*)d_in[27];
    float* out = (float*)d_out;

    k_main<<<NB, NTHREADS>>>(nf, ei, ets, tp, in_W, in_b, te_W1, te_b1, te_W2, te_b2,
                             aiW, aib, aoW, aob, ftW, ftb, opW, opb,
                             o1W, o1b, o2W, o2b, l1W, l1b, l2W, l2b, l3W, l3b, out);
}